// round 4
// baseline (speedup 1.0000x reference)
#include <cuda_runtime.h>
#include <cstdint>

#define BB 4
#define FF 3
#define NPTS 8192
#define DD 16
#define KNN_K 32
#define OO 64
#define ALPHA 0.2f
#define TILE 2048
#define WARPS_PER_BLK 16
#define PRE_BLOCKS 64           // 64 blocks x 512 thr = 32768 = B*N

// Scratch (device globals -- no allocations allowed)
__device__ float g_y1[BB * NPTS * OO];          // 8 MB: W1 . x[:,m]   layout [b][m][o]
__device__ float g_c [BB * NPTS * OO];          // 8 MB: (W2-W1).x[:,n] layout [b][n][o]
__device__ int   g_idx[BB * NPTS * KNN_K];      // 4 MB: knn indices

// ---------------------------------------------------------------------------
// Warp-cooperative sorted insert into lane-distributed top-32.
// Warp-converged: pass/bk/worst are all warp-uniform.
// ---------------------------------------------------------------------------
__device__ __forceinline__ void insert32(unsigned long long key,
                                         unsigned long long& listk,
                                         unsigned long long& worst,
                                         int lane)
{
    const unsigned FULL = 0xFFFFFFFFu;
    unsigned pass = __ballot_sync(FULL, key < worst);
    while (pass) {
        int src = __ffs(pass) - 1;
        pass &= pass - 1;
        unsigned long long bk = __shfl_sync(FULL, key, src);
        if (bk < worst) {                       // uniform branch
            unsigned long long up = __shfl_up_sync(FULL, listk, 1);
            bool gt   = listk > bk;
            bool upgt = (lane > 0) && (up > bk);
            if (gt) listk = upgt ? up : bk;
            worst = __shfl_sync(FULL, listk, 31);
        }
    }
}

// map float distance to order-preserving u32 (handles -0 / tiny negatives)
__device__ __forceinline__ unsigned mapf(float dpos)
{
    unsigned ub = __float_as_uint(dpos);
    return ub ^ (((unsigned)((int)ub >> 31)) | 0x80000000u);
}

// ---------------------------------------------------------------------------
// Fused kernel: blocks [0, PRE_BLOCKS) do the feature projections,
// blocks [PRE_BLOCKS, ...) do brute-force 32-NN (warp-per-query).
// The two halves are fully independent; fusing hides the projection
// under the knn waves.
//
// KNN distance arithmetic is bit-identical to the verified R1/R3 kernels:
//   xx[m] = fl(fl(fl(p0*p0)+fl(p1*p1))+fl(p2*p2))   (no fma)
//   dpos  = fl(xx[m] - fl(2*s - xx[n]))  computed as fsub(xxm, fma(s,2,-xxn))
//           (2*s exact; single rounding each step -> same bits as reference
//            negd with exact negation)
//   key   = <mapf(dpos), m>   unique; stable ties like lax.top_k
// ---------------------------------------------------------------------------
__global__ __launch_bounds__(512) void fused_pre_knn_kernel(
    const float* __restrict__ points,
    const float* __restrict__ x,
    const float* __restrict__ W)
{
    __shared__ float4 scand[TILE];              // 32 KB, knn blocks only
    __shared__ float  sW[OO * 2 * DD];          // 8 KB, precompute blocks only

    int tid = threadIdx.x;

    if (blockIdx.x < PRE_BLOCKS) {
        // ---------------- precompute: y1 / c projections ----------------
        for (int i = tid; i < OO * 2 * DD; i += 512) sW[i] = W[i];
        __syncthreads();

        int gid = blockIdx.x * 512 + tid;       // over B*N
        int b = gid / NPTS, n = gid % NPTS;

        float xv[DD];
#pragma unroll
        for (int d = 0; d < DD; d++) xv[d] = x[(b * DD + d) * NPTS + n];

        float* y1p = &g_y1[(b * NPTS + n) * OO];
        float* cp  = &g_c [(b * NPTS + n) * OO];
#pragma unroll 4
        for (int o = 0; o < OO; o++) {
            float s1 = 0.f, s2 = 0.f;
#pragma unroll
            for (int d = 0; d < DD; d++) {
                s1 = __fmaf_rn(sW[o * 2 * DD + d],      xv[d], s1);
                s2 = __fmaf_rn(sW[o * 2 * DD + DD + d], xv[d], s2);
            }
            y1p[o] = s1;
            cp[o]  = s2 - s1;
        }
        return;
    }

    // -------------------------- knn: warp-per-query ----------------------
    int bid  = blockIdx.x - PRE_BLOCKS;         // 0 .. B*(N/WPB)-1
    int b    = bid >> 9;                        // / (NPTS/WARPS_PER_BLK)
    int nblk = bid & 511;
    const float* pb = points + b * FF * NPTS;
    int wid  = tid >> 5;
    int lane = tid & 31;
    int n = nblk * WARPS_PER_BLK + wid;         // this warp's query

    float q0 = pb[n], q1 = pb[NPTS + n], q2 = pb[2 * NPTS + n];
    float xxn = __fadd_rn(__fadd_rn(__fmul_rn(q0, q0), __fmul_rn(q1, q1)),
                          __fmul_rn(q2, q2));
    float nxxn = -xxn;

    // sorted top-32, one key per lane; init keys larger than any real key
    unsigned long long listk = 0xFFFFFFFF00000000ULL | (unsigned)lane;
    unsigned long long worst = 0xFFFFFFFF0000001FULL;   // lane 31's key

    for (int t = 0; t < NPTS; t += TILE) {
        __syncthreads();
        // cooperative tile load: candidate coords + exact xx
        for (int i = tid; i < TILE; i += 512) {
            int m = t + i;
            float a0 = pb[m], a1 = pb[NPTS + m], a2 = pb[2 * NPTS + m];
            float xx = __fadd_rn(__fadd_rn(__fmul_rn(a0, a0), __fmul_rn(a1, a1)),
                                 __fmul_rn(a2, a2));
            scand[i] = make_float4(a0, a1, a2, xx);
        }
        __syncthreads();

        // 2 candidates per lane per iteration: independent chains for ILP
        for (int s = 0; s < TILE; s += 64) {
            float4 c1 = scand[s + lane];
            float4 c2 = scand[s + 32 + lane];

            float s1 = __fmul_rn(q0, c1.x);
            float s2 = __fmul_rn(q0, c2.x);
            s1 = __fmaf_rn(q1, c1.y, s1);
            s2 = __fmaf_rn(q1, c2.y, s2);
            s1 = __fmaf_rn(q2, c1.z, s1);
            s2 = __fmaf_rn(q2, c2.z, s2);
            float d1 = __fsub_rn(c1.w, __fmaf_rn(s1, 2.0f, nxxn));
            float d2 = __fsub_rn(c2.w, __fmaf_rn(s2, 2.0f, nxxn));

            unsigned long long key1 =
                ((unsigned long long)mapf(d1) << 32) | (unsigned)(t + s + lane);
            unsigned long long key2 =
                ((unsigned long long)mapf(d2) << 32) | (unsigned)(t + s + 32 + lane);

            insert32(key1, listk, worst, lane);
            insert32(key2, listk, worst, lane);
        }
    }

    // lane L holds L-th nearest (ascending dist, stable idx ties)
    g_idx[(b * NPTS + n) * KNN_K + lane] = (int)(listk & 0xFFFFFFFFu);
}

// ---------------------------------------------------------------------------
// Kernel 3: out[b][o][n] = (1/K) * sum_k leaky( y1[b][idx[n][k]][o] + c[b][n][o] )
// ---------------------------------------------------------------------------
__global__ __launch_bounds__(256) void edgeconv_kernel(float* __restrict__ out)
{
    __shared__ float stile[OO][33];
    __shared__ int   sidx[32 * KNN_K];

    int b = blockIdx.y;
    int nbase = blockIdx.x * 32;
    int tid = threadIdx.x;

    for (int i = tid; i < 32 * KNN_K; i += 256)
        sidx[i] = g_idx[(b * NPTS + nbase) * KNN_K + i];
    __syncthreads();

    int o = tid & 63;
    int sub = tid >> 6;

    for (int nt = 0; nt < 8; nt++) {
        int nl = nt * 4 + sub;
        int n = nbase + nl;
        float c = g_c[(b * NPTS + n) * OO + o];
        float acc = 0.f;
        const int* ip = &sidx[nl * KNN_K];
#pragma unroll 8
        for (int k = 0; k < KNN_K; k++) {
            int m = ip[k];
            float t = g_y1[(b * NPTS + m) * OO + o] + c;
            acc += (t >= 0.f) ? t : ALPHA * t;
        }
        stile[o][nl] = acc * (1.0f / KNN_K);
    }
    __syncthreads();

#pragma unroll
    for (int r = 0; r < 8; r++) {
        int oo = r * 8 + (tid >> 5);
        int nn = tid & 31;
        out[(b * OO + oo) * NPTS + nbase + nn] = stile[oo][nn];
    }
}

// ---------------------------------------------------------------------------
extern "C" void kernel_launch(void* const* d_in, const int* in_sizes, int n_in,
                              void* d_out, int out_size)
{
    const float* points = nullptr;
    const float* x = nullptr;
    const float* W = nullptr;
    for (int i = 0; i < n_in; i++) {
        if      (in_sizes[i] == BB * FF * NPTS) points = (const float*)d_in[i];
        else if (in_sizes[i] == BB * DD * NPTS) x      = (const float*)d_in[i];
        else if (in_sizes[i] == OO * 2 * DD)    W      = (const float*)d_in[i];
    }
    float* out = (float*)d_out;

    int knn_blocks = BB * (NPTS / WARPS_PER_BLK);     // 2048
    fused_pre_knn_kernel<<<PRE_BLOCKS + knn_blocks, 512>>>(points, x, W);

    edgeconv_kernel<<<dim3(NPTS / 32, BB), 256>>>(out);
}

// round 5
// speedup vs baseline: 1.2467x; 1.2467x over previous
#include <cuda_runtime.h>
#include <cstdint>

#define BB 4
#define FF 3
#define NPTS 8192
#define DD 16
#define KNN_K 32
#define OO 64
#define ALPHA 0.2f

#define NB 256                      // x-axis buckets
#define XMINV (-5.0f)
#define BWID 0.0390625f             // 10/256, exact binary (5*2^-7)
#define INV_BWID 25.6f
#define PRUNE_MARGIN 1e-3f

#define KNN_WARPS 8                 // warps per knn block
#define PRE_BLOCKS 128              // 128 * 256 = 32768 = B*N

// Scratch (device globals -- no allocations allowed)
__device__ float  g_y1[BB * NPTS * OO];         // W1 . x[:,m]       [b][m][o]
__device__ float  g_c [BB * NPTS * OO];         // (W2-W1).x[:,n]    [b][n][o]
__device__ int    g_idx[BB * NPTS * KNN_K];     // knn indices
__device__ float4 g_spts[BB * NPTS];            // x-sorted (p0,p1,p2, idx-bits)
__device__ int    g_bstart[BB * (NB + 1)];      // bucket CSR offsets

// ---------------------------------------------------------------------------
__device__ __forceinline__ int bucket_of(float xv)
{
    int bk = (int)floorf((xv - XMINV) * INV_BWID);
    return min(max(bk, 0), NB - 1);
}

// order-preserving float->u32 map and inverse
__device__ __forceinline__ unsigned mapf(float dpos)
{
    unsigned ub = __float_as_uint(dpos);
    return ub ^ (((unsigned)((int)ub >> 31)) | 0x80000000u);
}
__device__ __forceinline__ float unmapf(unsigned m)
{
    unsigned ub = (m & 0x80000000u) ? (m ^ 0x80000000u) : ~m;
    return __uint_as_float(ub);
}

// Warp-cooperative sorted insert into lane-distributed top-32 (warp-converged).
__device__ __forceinline__ void insert32(unsigned long long key,
                                         unsigned long long& listk,
                                         unsigned long long& worst,
                                         int lane)
{
    const unsigned FULL = 0xFFFFFFFFu;
    unsigned pass = __ballot_sync(FULL, key < worst);
    while (pass) {
        int src = __ffs(pass) - 1;
        pass &= pass - 1;
        unsigned long long bk = __shfl_sync(FULL, key, src);
        if (bk < worst) {                       // uniform branch
            unsigned long long up = __shfl_up_sync(FULL, listk, 1);
            bool gt   = listk > bk;
            bool upgt = (lane > 0) && (up > bk);
            if (gt) listk = upgt ? up : bk;
            worst = __shfl_sync(FULL, listk, 31);
        }
    }
}

// ---------------------------------------------------------------------------
// Kernel A: per-batch counting sort of points by x into NB buckets.
// Stores (p0,p1,p2, idx-bits) per point; xx is recomputed exactly in knn.
// ---------------------------------------------------------------------------
__global__ __launch_bounds__(512) void sort_kernel(const float* __restrict__ points)
{
    __shared__ int hist[NB];
    int b = blockIdx.x;
    int tid = threadIdx.x;
    const float* pb = points + b * FF * NPTS;

    for (int j = tid; j < NB; j += 512) hist[j] = 0;
    __syncthreads();

    for (int m = tid; m < NPTS; m += 512)
        atomicAdd(&hist[bucket_of(pb[m])], 1);
    __syncthreads();

    if (tid == 0) {                 // serial scan over 256 bins: cheap
        int run = 0;
        for (int j = 0; j < NB; j++) {
            int c = hist[j];
            g_bstart[b * (NB + 1) + j] = run;
            hist[j] = run;          // becomes scatter cursor
            run += c;
        }
        g_bstart[b * (NB + 1) + NB] = run;
    }
    __syncthreads();

    for (int m = tid; m < NPTS; m += 512) {
        float a0 = pb[m];
        int bk = bucket_of(a0);
        int pos = atomicAdd(&hist[bk], 1);
        g_spts[b * NPTS + pos] =
            make_float4(a0, pb[NPTS + m], pb[2 * NPTS + m], __int_as_float(m));
    }
}

// ---------------------------------------------------------------------------
// Kernel B (fused): blocks [0,PRE_BLOCKS) do feature projections (independent
// of the sort); remaining blocks do pruned 32-NN, warp-per-query.
//
// Distance arithmetic bit-identical to verified rounds:
//   xx    = fl(fl(fl(p0^2)+fl(p1^2))+fl(p2^2))
//   dpos  = fsub(xx_m, fma(s, 2, -xx_n))     (== reference negd negated)
//   key   = <mapf(dpos), idx>                (unique; stable ties)
// Bucket walk outward from the query bucket; a side stops when the exact
// axis lower bound exceeds worst_dist + margin. Sentinel worst -> NaN ->
// no early stop until 32 real neighbors are held. Order-invariant selection
// => identical result to brute force.
// ---------------------------------------------------------------------------
__global__ __launch_bounds__(256) void fused_pre_knn_kernel(
    const float* __restrict__ points,
    const float* __restrict__ x,
    const float* __restrict__ W)
{
    __shared__ float sW[OO * 2 * DD];           // precompute blocks
    __shared__ int   sbs[NB + 1];               // knn blocks: bucket CSR

    int tid = threadIdx.x;

    if (blockIdx.x < PRE_BLOCKS) {
        // ---------------- precompute: y1 / c projections ----------------
        for (int i = tid; i < OO * 2 * DD; i += 256) sW[i] = W[i];
        __syncthreads();

        int gid = blockIdx.x * 256 + tid;       // over B*N
        int b = gid / NPTS, n = gid % NPTS;

        float xv[DD];
#pragma unroll
        for (int d = 0; d < DD; d++) xv[d] = x[(b * DD + d) * NPTS + n];

        float* y1p = &g_y1[(b * NPTS + n) * OO];
        float* cp  = &g_c [(b * NPTS + n) * OO];
#pragma unroll 4
        for (int o = 0; o < OO; o++) {
            float s1 = 0.f, s2 = 0.f;
#pragma unroll
            for (int d = 0; d < DD; d++) {
                s1 = __fmaf_rn(sW[o * 2 * DD + d],      xv[d], s1);
                s2 = __fmaf_rn(sW[o * 2 * DD + DD + d], xv[d], s2);
            }
            y1p[o] = s1;
            cp[o]  = s2 - s1;
        }
        return;
    }

    // ------------------------ knn: warp-per-query ------------------------
    int bid  = blockIdx.x - PRE_BLOCKS;         // 0 .. B*(N/KNN_WARPS)-1
    int b    = bid >> 10;                       // / (NPTS/KNN_WARPS = 1024)
    int nblk = bid & 1023;
    int wid  = tid >> 5;
    int lane = tid & 31;
    int n = nblk * KNN_WARPS + wid;

    for (int j = tid; j < NB + 1; j += 256)
        sbs[j] = g_bstart[b * (NB + 1) + j];
    __syncthreads();

    const float*  pb = points + b * FF * NPTS;
    const float4* sp = g_spts + b * NPTS;

    float q0 = pb[n], q1 = pb[NPTS + n], q2 = pb[2 * NPTS + n];
    float xxn = __fadd_rn(__fadd_rn(__fmul_rn(q0, q0), __fmul_rn(q1, q1)),
                          __fmul_rn(q2, q2));
    float nxxn = -xxn;

    unsigned long long listk = 0xFFFFFFFF00000000ULL | (unsigned)lane;
    unsigned long long worst = 0xFFFFFFFF0000001FULL;

    auto process = [&](int j) {
        int s0 = sbs[j], s1e = sbs[j + 1];
        for (int g = s0; g < s1e; g += 32) {
            int i = g + lane;
            unsigned long long key = 0xFFFFFFFFFFFFFFFFULL;
            if (i < s1e) {
                float4 c = __ldg(&sp[i]);
                float xxm = __fadd_rn(
                    __fadd_rn(__fmul_rn(c.x, c.x), __fmul_rn(c.y, c.y)),
                    __fmul_rn(c.z, c.z));
                float ss = __fmul_rn(q0, c.x);
                ss = __fmaf_rn(q1, c.y, ss);
                ss = __fmaf_rn(q2, c.z, ss);
                float d = __fsub_rn(xxm, __fmaf_rn(ss, 2.0f, nxxn));
                key = ((unsigned long long)mapf(d) << 32) |
                      (unsigned)__float_as_int(c.w);
            }
            insert32(key, listk, worst, lane);
        }
    };

    int qb = bucket_of(q0);
    process(qb);

    int l = qb - 1, r = qb + 1;
    bool goL = (l >= 0), goR = (r < NB);
    while (goL || goR) {
        float worstd = unmapf((unsigned)(worst >> 32));  // NaN while sentinels
        if (goR) {
            float dxr = __fsub_rn(XMINV + (float)r * BWID, q0);
            if (__fmul_rn(dxr, dxr) > worstd + PRUNE_MARGIN) goR = false;
            else { process(r); r++; goR = (r < NB); }
        }
        if (goL) {
            float worstd2 = unmapf((unsigned)(worst >> 32));
            float dxl = __fsub_rn(q0, XMINV + (float)(l + 1) * BWID);
            if (__fmul_rn(dxl, dxl) > worstd2 + PRUNE_MARGIN) goL = false;
            else { process(l); l--; goL = (l >= 0); }
        }
    }

    // lane L holds L-th nearest (ascending dist, stable idx ties)
    g_idx[(b * NPTS + n) * KNN_K + lane] = (int)(listk & 0xFFFFFFFFu);
}

// ---------------------------------------------------------------------------
// Kernel 3: out[b][o][n] = (1/K) * sum_k leaky( y1[b][idx[n][k]][o] + c[b][n][o] )
// ---------------------------------------------------------------------------
__global__ __launch_bounds__(256) void edgeconv_kernel(float* __restrict__ out)
{
    __shared__ float stile[OO][33];
    __shared__ int   sidx[32 * KNN_K];

    int b = blockIdx.y;
    int nbase = blockIdx.x * 32;
    int tid = threadIdx.x;

    for (int i = tid; i < 32 * KNN_K; i += 256)
        sidx[i] = g_idx[(b * NPTS + nbase) * KNN_K + i];
    __syncthreads();

    int o = tid & 63;
    int sub = tid >> 6;

    for (int nt = 0; nt < 8; nt++) {
        int nl = nt * 4 + sub;
        int n = nbase + nl;
        float c = g_c[(b * NPTS + n) * OO + o];
        float acc = 0.f;
        const int* ip = &sidx[nl * KNN_K];
#pragma unroll 8
        for (int k = 0; k < KNN_K; k++) {
            int m = ip[k];
            float t = g_y1[(b * NPTS + m) * OO + o] + c;
            acc += (t >= 0.f) ? t : ALPHA * t;
        }
        stile[o][nl] = acc * (1.0f / KNN_K);
    }
    __syncthreads();

#pragma unroll
    for (int r = 0; r < 8; r++) {
        int oo = r * 8 + (tid >> 5);
        int nn = tid & 31;
        out[(b * OO + oo) * NPTS + nbase + nn] = stile[oo][nn];
    }
}

// ---------------------------------------------------------------------------
extern "C" void kernel_launch(void* const* d_in, const int* in_sizes, int n_in,
                              void* d_out, int out_size)
{
    const float* points = nullptr;
    const float* x = nullptr;
    const float* W = nullptr;
    for (int i = 0; i < n_in; i++) {
        if      (in_sizes[i] == BB * FF * NPTS) points = (const float*)d_in[i];
        else if (in_sizes[i] == BB * DD * NPTS) x      = (const float*)d_in[i];
        else if (in_sizes[i] == OO * 2 * DD)    W      = (const float*)d_in[i];
    }
    float* out = (float*)d_out;

    sort_kernel<<<BB, 512>>>(points);

    int knn_blocks = BB * (NPTS / KNN_WARPS);          // 4096
    fused_pre_knn_kernel<<<PRE_BLOCKS + knn_blocks, 256>>>(points, x, W);

    edgeconv_kernel<<<dim3(NPTS / 32, BB), 256>>>(out);
}